// round 14
// baseline (speedup 1.0000x reference)
#include <cuda_runtime.h>
#include <cuda_bf16.h>
#include <math.h>

#define B_   2
#define L_   1408
#define D_   512
#define H_   8
#define BH_  16
#define DFF_ 2048
#define BL_  (B_*L_)
#define KSEL_ 704

// ---------------- scratch ----------------
__device__ __nv_bfloat16 g_xnh[BL_*D_];               // LN1 output, bf16 (feeds xp only)
__device__ float g_q[BH_*L_*64];
__device__ float g_k[BH_*L_*64];
__device__ float g_adj[(size_t)BH_*L_*L_];
__device__ __nv_bfloat16 g_adjh[(size_t)BH_*L_*L_];   // softmaxed adj, bf16
__device__ float g_xp[BL_*D_];
__device__ float g_gout[4][BL_*D_];                   // split-K partials
__device__ float g_x1[BL_*D_];
__device__ __nv_bfloat16 g_xn2h[BL_*D_];              // LN2 output, bf16
__device__ __nv_bfloat16 g_ffhh[(size_t)BL_*DFF_];    // gelu(ffn1), bf16
__device__ __nv_bfloat16 g_w1t[DFF_*D_];              // w_f1^T bf16
__device__ __nv_bfloat16 g_w2t[D_*DFF_];              // w_f2^T bf16
__device__ __nv_bfloat16 g_wgt[D_*D_];                // w_gcn^T bf16
__device__ float g_spz[L_*3];
__device__ float g_ent[1];

// ---------------- helpers ----------------
__device__ __forceinline__ float blk_sum(float v, float* s){
    int lane = threadIdx.x & 31, w = threadIdx.x >> 5;
    #pragma unroll
    for(int o=16;o;o>>=1) v += __shfl_down_sync(0xffffffffu, v, o);
    if(lane==0) s[w]=v;
    __syncthreads();
    int nw = blockDim.x >> 5;
    v = (threadIdx.x < nw) ? s[threadIdx.x] : 0.f;
    if(w==0){
        #pragma unroll
        for(int o=16;o;o>>=1) v += __shfl_down_sync(0xffffffffu, v, o);
        if(lane==0) s[0]=v;
    }
    __syncthreads();
    float r = s[0];
    __syncthreads();
    return r;
}

__device__ __forceinline__ void blk_sum3(float z0, float z1, float z2, float* r3){
    int lane = threadIdx.x & 31, w = threadIdx.x >> 5;
    #pragma unroll
    for(int o=16;o;o>>=1){
        z0 += __shfl_down_sync(0xffffffffu, z0, o);
        z1 += __shfl_down_sync(0xffffffffu, z1, o);
        z2 += __shfl_down_sync(0xffffffffu, z2, o);
    }
    if(lane==0){ r3[3+w]=z0; r3[11+w]=z1; r3[19+w]=z2; }
    __syncthreads();
    if(threadIdx.x==0){
        float a=0,b=0,c=0;
        #pragma unroll
        for(int i=0;i<8;i++){ a+=r3[3+i]; b+=r3[11+i]; c+=r3[19+i]; }
        r3[0]=a; r3[1]=b; r3[2]=c;
    }
    __syncthreads();
}

__device__ __forceinline__ float geluf(float x){
    return 0.5f * x * (1.0f + erff(x * 0.7071067811865475f));
}

__device__ __forceinline__ unsigned tokey(float f){
    unsigned u = __float_as_uint(f);
    return (u & 0x80000000u) ? ~u : (u | 0x80000000u);
}

__device__ __forceinline__ void cpa16(void* s, const void* g){
    unsigned sa = (unsigned)__cvta_generic_to_shared(s);
    asm volatile("cp.async.cg.shared.global [%0], [%1], 16;" :: "r"(sa), "l"(g));
}
__device__ __forceinline__ void cp_commit(){ asm volatile("cp.async.commit_group;"); }
__device__ __forceinline__ void cp_wait0(){ asm volatile("cp.async.wait_group 0;"); }

__device__ __forceinline__ void mma_tf32(float c[4], unsigned a0, unsigned a1, unsigned a2, unsigned a3,
                                         unsigned b0, unsigned b1){
    asm volatile("mma.sync.aligned.m16n8k8.row.col.f32.tf32.tf32.f32 "
        "{%0,%1,%2,%3}, {%4,%5,%6,%7}, {%8,%9}, {%0,%1,%2,%3};"
        : "+f"(c[0]), "+f"(c[1]), "+f"(c[2]), "+f"(c[3])
        : "r"(a0), "r"(a1), "r"(a2), "r"(a3), "r"(b0), "r"(b1));
}

__device__ __forceinline__ void mma_bf16(float c[4], unsigned a0, unsigned a1, unsigned a2, unsigned a3,
                                         unsigned b0, unsigned b1){
    asm volatile("mma.sync.aligned.m16n8k16.row.col.f32.bf16.bf16.f32 "
        "{%0,%1,%2,%3}, {%4,%5,%6,%7}, {%8,%9}, {%0,%1,%2,%3};"
        : "+f"(c[0]), "+f"(c[1]), "+f"(c[2]), "+f"(c[3])
        : "r"(a0), "r"(a1), "r"(a2), "r"(a3), "r"(b0), "r"(b1));
}

// ---------------- tf32 GEMM (adj only now) ----------------
template<int BM, int BN, int BLAYOUT, int ACT, int RES, int BIAS, int SPLITK>
__global__ void __launch_bounds__(256)
mma_gemm(const float* __restrict__ A, const float* __restrict__ Bsrc,
         const float* __restrict__ bias, const float* __restrict__ res,
         float* __restrict__ C,
         int K, int lda, int ldb, int ldc,
         int zdiv, size_t aB, size_t bOut, size_t bIn,
         size_t cOut, size_t cIn, size_t cSplit)
{
    constexpr int WROWS = BM/32;
    constexpr int WCOLS = 8/WROWS;
    constexpr int NW    = BN/WCOLS;
    constexpr int NFRAG = NW/8;
    constexpr int ASZ = BM*36;
    constexpr int BSZ = (BLAYOUT==1) ? BN*36 : 32*(BN+4);
    constexpr int BNQ = BN/4;
    extern __shared__ float smem[];
    float* As = smem;
    float* Bs = smem + 2*ASZ;

    int z = blockIdx.z;
    const float* Ap = A + (size_t)z*aB;
    const float* Bp = Bsrc + (size_t)(z/zdiv)*bOut + (size_t)(z%zdiv)*bIn;
    const float* resp = RES ? (res + (size_t)(z/zdiv)*cOut + (size_t)(z%zdiv)*cIn) : nullptr;
    float* Cp = C + (size_t)(z/zdiv)*cOut + (size_t)(z%zdiv)*cIn;

    int n0, kBase = 0;
    if(SPLITK > 1){ n0 = 0; kBase = blockIdx.x * K; Cp += (size_t)blockIdx.x * cSplit; }
    else n0 = blockIdx.x*BN;
    int m0 = blockIdx.y*BM;
    int t = threadIdx.x, warp = t>>5, lane = t&31;
    int g = lane>>2, tg = lane&3;
    int wm = (warp/WCOLS)*32, wn = (warp%WCOLS)*NW;

    float acc[2][NFRAG][4] = {};

    auto load_tiles = [&](int buf, int k0){
        float* Ad = As + buf*ASZ;
        float* Bd = Bs + buf*BSZ;
        #pragma unroll
        for(int j=0; j<BM/32; j++){
            int i = t + j*256;
            int m = i>>3, k4 = (i&7)<<2;
            cpa16(&Ad[m*36+k4], Ap + (size_t)(m0+m)*lda + k0 + k4);
        }
        if(BLAYOUT==1){
            #pragma unroll
            for(int j=0; j<BN/32; j++){
                int i = t + j*256;
                int n = i>>3, k4 = (i&7)<<2;
                cpa16(&Bd[n*36+k4], Bp + (size_t)(n0+n)*ldb + k0 + k4);
            }
        } else {
            #pragma unroll
            for(int j=0; j<BN/32; j++){
                int i = t + j*256;
                int k = i/BNQ, n4 = (i%BNQ)*4;
                cpa16(&Bd[k*(BN+4)+n4], Bp + (size_t)(k0+k)*ldb + n0 + n4);
            }
        }
        cp_commit();
    };

    int nIter = K/32;
    load_tiles(0, kBase);
    for(int it=0; it<nIter; it++){
        cp_wait0();
        __syncthreads();
        if(it+1 < nIter) load_tiles((it+1)&1, kBase + (it+1)*32);
        int buf = it&1;
        const float* Ab = As + buf*ASZ;
        const float* Bb = Bs + buf*BSZ;
        #pragma unroll
        for(int ks=0; ks<32; ks+=8){
            unsigned a[2][4];
            #pragma unroll
            for(int mi=0; mi<2; mi++){
                int r0 = wm + mi*16 + g;
                a[mi][0] = __float_as_uint(Ab[r0*36     + ks+tg]);
                a[mi][1] = __float_as_uint(Ab[(r0+8)*36 + ks+tg]);
                a[mi][2] = __float_as_uint(Ab[r0*36     + ks+tg+4]);
                a[mi][3] = __float_as_uint(Ab[(r0+8)*36 + ks+tg+4]);
            }
            #pragma unroll
            for(int nj=0; nj<NFRAG; nj++){
                int n = wn + nj*8 + g;
                unsigned b0, b1;
                if(BLAYOUT==1){ b0 = __float_as_uint(Bb[n*36 + ks+tg]);
                                b1 = __float_as_uint(Bb[n*36 + ks+tg+4]); }
                else          { b0 = __float_as_uint(Bb[(ks+tg)*(BN+4) + n]);
                                b1 = __float_as_uint(Bb[(ks+tg+4)*(BN+4) + n]); }
                #pragma unroll
                for(int mi=0; mi<2; mi++)
                    mma_tf32(acc[mi][nj], a[mi][0],a[mi][1],a[mi][2],a[mi][3], b0,b1);
            }
        }
        __syncthreads();
    }

    #pragma unroll
    for(int mi=0; mi<2; mi++){
        #pragma unroll
        for(int nj=0; nj<NFRAG; nj++){
            int col = n0 + wn + nj*8 + tg*2;
            #pragma unroll
            for(int half=0; half<2; half++){
                int m = m0 + wm + mi*16 + g + half*8;
                float v0 = acc[mi][nj][half*2+0];
                float v1 = acc[mi][nj][half*2+1];
                if(BIAS){ v0 += bias[col]; v1 += bias[col+1]; }
                if(ACT){ v0 = geluf(v0); v1 = geluf(v1); }
                if(RES){
                    v0 += resp[(size_t)m*ldc + col];
                    v1 += resp[(size_t)m*ldc + col+1];
                }
                *(float2*)(Cp + (size_t)m*ldc + col) = make_float2(v0, v1);
            }
        }
    }
}

template<int BM, int BN, int BLAYOUT>
constexpr int gemm_smem(){
    return (2*BM*36 + 2*((BLAYOUT==1) ? BN*36 : 32*(BN+4))) * 4;
}

// ---------------- bf16 m16n8k16 GEMM. A [m][k] bf16, Bn [n][k] bf16, BN=64, BK=64 ----------------
template<int BM, int ACT, int RES, int BIAS, int OUTBF>
__global__ void __launch_bounds__(256)
hgemm(const __nv_bfloat16* __restrict__ A, const __nv_bfloat16* __restrict__ Bn,
      const float* __restrict__ bias, const float* __restrict__ res,
      void* __restrict__ Cv, int K, int lda, int ldb, int ldc)
{
    constexpr int WROWS = BM/32;
    constexpr int WCOLS = 8/WROWS;
    constexpr int NW    = 64/WCOLS;
    constexpr int NFRAG = NW/8;
    constexpr int ASZ = BM*72;
    constexpr int BSZ = 64*72;
    extern __shared__ __nv_bfloat16 hsm[];
    __nv_bfloat16* As = hsm;
    __nv_bfloat16* Bs = hsm + 2*ASZ;

    int n0 = blockIdx.x*64, m0 = blockIdx.y*BM;
    int t = threadIdx.x, warp = t>>5, lane = t&31;
    int g = lane>>2, tg = lane&3;
    int wm = (warp/WCOLS)*32, wn = (warp%WCOLS)*NW;
    float acc[2][NFRAG][4] = {};

    auto load_tiles = [&](int buf, int k0){
        __nv_bfloat16* Ad = As + buf*ASZ;
        __nv_bfloat16* Bd = Bs + buf*BSZ;
        #pragma unroll
        for(int j=0; j<BM/32; j++){
            int i = t + j*256;
            int m = i>>3, kc = (i&7)*8;
            cpa16(&Ad[m*72+kc], A + (size_t)(m0+m)*lda + k0 + kc);
        }
        #pragma unroll
        for(int j=0; j<2; j++){
            int i = t + j*256;
            int n = i>>3, kc = (i&7)*8;
            cpa16(&Bd[n*72+kc], Bn + (size_t)(n0+n)*ldb + k0 + kc);
        }
        cp_commit();
    };

    int nIter = K/64;
    load_tiles(0, 0);
    for(int it=0; it<nIter; it++){
        cp_wait0();
        __syncthreads();
        if(it+1 < nIter) load_tiles((it+1)&1, (it+1)*64);
        int buf = it&1;
        const __nv_bfloat16* Ab = As + buf*ASZ;
        const __nv_bfloat16* Bb = Bs + buf*BSZ;
        #pragma unroll
        for(int ks=0; ks<64; ks+=16){
            unsigned a[2][4];
            #pragma unroll
            for(int mi=0; mi<2; mi++){
                int r0 = wm + mi*16 + g;
                a[mi][0] = *(const unsigned*)(Ab + r0*72     + ks + 2*tg);
                a[mi][1] = *(const unsigned*)(Ab + (r0+8)*72 + ks + 2*tg);
                a[mi][2] = *(const unsigned*)(Ab + r0*72     + ks + 2*tg + 8);
                a[mi][3] = *(const unsigned*)(Ab + (r0+8)*72 + ks + 2*tg + 8);
            }
            #pragma unroll
            for(int nj=0; nj<NFRAG; nj++){
                int n = wn + nj*8 + g;
                unsigned b0 = *(const unsigned*)(Bb + n*72 + ks + 2*tg);
                unsigned b1 = *(const unsigned*)(Bb + n*72 + ks + 2*tg + 8);
                #pragma unroll
                for(int mi=0; mi<2; mi++)
                    mma_bf16(acc[mi][nj], a[mi][0],a[mi][1],a[mi][2],a[mi][3], b0,b1);
            }
        }
        __syncthreads();
    }

    #pragma unroll
    for(int mi=0; mi<2; mi++){
        #pragma unroll
        for(int nj=0; nj<NFRAG; nj++){
            int col = n0 + wn + nj*8 + tg*2;
            #pragma unroll
            for(int half=0; half<2; half++){
                int m = m0 + wm + mi*16 + g + half*8;
                float v0 = acc[mi][nj][half*2+0];
                float v1 = acc[mi][nj][half*2+1];
                if(BIAS){ v0 += bias[col]; v1 += bias[col+1]; }
                if(ACT){ v0 = geluf(v0); v1 = geluf(v1); }
                if(RES){
                    v0 += res[(size_t)m*ldc + col];
                    v1 += res[(size_t)m*ldc + col+1];
                }
                if(OUTBF){
                    __nv_bfloat162 pv = __floats2bfloat162_rn(v0, v1);
                    *(__nv_bfloat162*)((__nv_bfloat16*)Cv + (size_t)m*ldc + col) = pv;
                } else {
                    *(float2*)((float*)Cv + (size_t)m*ldc + col) = make_float2(v0, v1);
                }
            }
        }
    }
}

template<int BM>
constexpr int hgemm_smem(){ return (2*BM*72 + 2*64*72) * 2; }

// ---------------- transpose + fp32->bf16 convert: dst[c][r] = bf16(src[r][c]) ----------------
__global__ void tcvt_kernel(const float* __restrict__ src, __nv_bfloat16* __restrict__ dst,
                            int R, int C){
    __shared__ float tile[32][33];
    int t = threadIdx.x;
    int tc = t & 31, tr = t >> 5;
    int rb = blockIdx.y*32, cb = blockIdx.x*32;
    #pragma unroll
    for(int j=0;j<4;j++){
        int rl = tr + j*8;
        tile[rl][tc] = src[(size_t)(rb+rl)*C + cb + tc];
    }
    __syncthreads();
    #pragma unroll
    for(int j=0;j<4;j++){
        int cl = tr + j*8;
        dst[(size_t)(cb+cl)*R + rb + tc] = __float2bfloat16(tile[tc][cl]);
    }
}

// ---------------- gconv: A = bf16 adj, B = fp32 xp, tf32 MMA, split-K=4 ----------------
__global__ void __launch_bounds__(256)
gconv_kernel(){
    constexpr int ASZ = 128*36;
    constexpr int BSZ = 32*68;
    extern __shared__ float smem[];
    float* As = smem;
    float* Bs = smem + 2*ASZ;

    int bh = blockIdx.z, b = bh >> 3, h = bh & 7;
    int m0 = blockIdx.y*128;
    int kBase = blockIdx.x*352;
    const __nv_bfloat16* Ap = g_adjh + ((size_t)bh*L_ + m0)*L_;
    const float* Bp = g_xp + (size_t)b*L_*D_ + h*64;
    float* Cp = g_gout[blockIdx.x] + ((size_t)b*L_ + m0)*D_ + h*64;

    int t = threadIdx.x, warp = t>>5, lane = t&31;
    int g = lane>>2, tg = lane&3;
    int wm = (warp>>1)*32, wn = (warp&1)*32;
    float acc[2][4][4] = {};

    int am = t>>1, ak = (t&1)*16;
    uint4 areg0, areg1;
    auto ldgA = [&](int k0){
        const __nv_bfloat16* p = Ap + (size_t)am*L_ + k0 + ak;
        areg0 = *(const uint4*)(p);
        areg1 = *(const uint4*)(p+8);
    };
    auto stsA = [&](int buf){
        float* Ad = As + buf*ASZ + am*36 + ak;
        unsigned u[8] = {areg0.x,areg0.y,areg0.z,areg0.w, areg1.x,areg1.y,areg1.z,areg1.w};
        float f[16];
        #pragma unroll
        for(int q=0;q<8;q++){
            __nv_bfloat162 hv = *reinterpret_cast<__nv_bfloat162*>(&u[q]);
            float2 fv = __bfloat1622float2(hv);
            f[q*2]=fv.x; f[q*2+1]=fv.y;
        }
        #pragma unroll
        for(int q=0;q<4;q++)
            *(float4*)(Ad + q*4) = make_float4(f[q*4],f[q*4+1],f[q*4+2],f[q*4+3]);
    };
    auto ldB = [&](int buf, int k0){
        float* Bd = Bs + buf*BSZ;
        #pragma unroll
        for(int j=0;j<2;j++){
            int i = t + j*256;
            int k = i>>4, n4 = (i&15)<<2;
            cpa16(&Bd[k*68+n4], Bp + (size_t)(k0+k)*D_ + n4);
        }
        cp_commit();
    };

    ldgA(kBase);
    ldB(0, kBase);
    for(int it=0; it<11; it++){
        stsA(it&1);
        cp_wait0();
        __syncthreads();
        if(it+1 < 11){ ldgA(kBase + (it+1)*32); ldB((it+1)&1, kBase + (it+1)*32); }
        int buf = it&1;
        const float* Ab = As + buf*ASZ;
        const float* Bb = Bs + buf*BSZ;
        #pragma unroll
        for(int ks=0; ks<32; ks+=8){
            unsigned a[2][4];
            #pragma unroll
            for(int mi=0; mi<2; mi++){
                int r0 = wm + mi*16 + g;
                a[mi][0] = __float_as_uint(Ab[r0*36     + ks+tg]);
                a[mi][1] = __float_as_uint(Ab[(r0+8)*36 + ks+tg]);
                a[mi][2] = __float_as_uint(Ab[r0*36     + ks+tg+4]);
                a[mi][3] = __float_as_uint(Ab[(r0+8)*36 + ks+tg+4]);
            }
            #pragma unroll
            for(int nj=0; nj<4; nj++){
                int n = wn + nj*8 + g;
                unsigned b0 = __float_as_uint(Bb[(ks+tg)*68 + n]);
                unsigned b1 = __float_as_uint(Bb[(ks+tg+4)*68 + n]);
                #pragma unroll
                for(int mi=0; mi<2; mi++)
                    mma_tf32(acc[mi][nj], a[mi][0],a[mi][1],a[mi][2],a[mi][3], b0,b1);
            }
        }
        __syncthreads();
    }

    #pragma unroll
    for(int mi=0; mi<2; mi++){
        #pragma unroll
        for(int nj=0; nj<4; nj++){
            int col = wn + nj*8 + tg*2;
            #pragma unroll
            for(int half=0; half<2; half++){
                int m = wm + mi*16 + g + half*8;
                *(float2*)(Cp + (size_t)m*D_ + col) =
                    make_float2(acc[mi][nj][half*2+0], acc[mi][nj][half*2+1]);
            }
        }
    }
}
constexpr int GCONV_SMEM = (2*128*36 + 2*32*68) * 4;

// ---------------- fused LN1 + q/k projection + stat zeroing (xn out bf16) ----------------
__global__ void ln1qk_kernel(const float* __restrict__ x, const float* __restrict__ g,
                             const float* __restrict__ bta,
                             const float* __restrict__ w1, const float* __restrict__ b1,
                             const float* __restrict__ w2, const float* __restrict__ b2){
    __shared__ float xr[512];
    __shared__ float W1[4096];
    __shared__ float W2[4096];
    __shared__ float s[32];
    int row = blockIdx.x;
    int t = threadIdx.x;                 // 512
    float v = x[(size_t)row*D_ + t];
    for(int i=t;i<4096;i+=512){ W1[i]=w1[i]; W2[i]=w2[i]; }
    float mean = blk_sum(v, s) * (1.f/D_);
    float d = v - mean;
    float var = blk_sum(d*d, s) * (1.f/D_);
    float inv = rsqrtf(var + 1e-5f);
    float xnv = d*inv*g[t] + bta[t];
    xr[t] = xnv;
    g_xnh[(size_t)row*D_ + t] = __float2bfloat16(xnv);
    __syncthreads();
    int h = t >> 6, j = t & 63;
    const float* xv = xr + h*64;
    float a1 = b1[j], a2 = b2[j];
    #pragma unroll
    for(int d2=0; d2<64; d2++){
        float vv = xv[d2];
        a1 += vv * W1[d2*64+j];
        a2 += vv * W2[d2*64+j];
    }
    int b = row / L_, l = row % L_;
    size_t o = (((size_t)b*H_ + h)*L_ + l)*64 + j;
    g_q[o] = a1; g_k[o] = a2;
    if(row == 0){
        for(int i=t;i<L_*3;i+=512) g_spz[i] = 0.f;
        if(t == 0) g_ent[0] = 0.f;
    }
}

// fused: top-k sparsify + MoE gating + loss stats + mask mix + row softmax (bf16 out)
// register-resident; warp-aggregated histogram atomics.
__global__ void __launch_bounds__(256)
topk_gate_fin_kernel(const float* __restrict__ w_gate,
                     const float* __restrict__ masks){
    __shared__ unsigned hist[256];
    __shared__ unsigned wsum[8];
    __shared__ float rs[32];
    __shared__ unsigned sel[3];
    __shared__ unsigned skt;
    __shared__ float sgv[3];
    int row = blockIdx.x;         // bh*L + l
    int l = row % L_;
    int t = threadIdx.x;          // 256
    int lane = t & 31, w = t >> 5;
    float* grow = g_adj + (size_t)row*L_;
    __nv_bfloat16* hrow = g_adjh + (size_t)row*L_;
    bool act1 = (t < 96);         // warp-uniform (warps 0-2)
    int i0 = 4*t, i1 = 1024 + 4*t;

    float val[8];
    unsigned key[8];
    {
        float4 v0 = *(const float4*)(grow + i0);
        val[0]=v0.x; val[1]=v0.y; val[2]=v0.z; val[3]=v0.w;
        if(act1){
            float4 v1 = *(const float4*)(grow + i1);
            val[4]=v1.x; val[5]=v1.y; val[6]=v1.z; val[7]=v1.w;
        } else { val[4]=val[5]=val[6]=val[7]=0.f; }
        #pragma unroll
        for(int j=0;j<8;j++) key[j] = tokey(val[j]);
    }

    unsigned prefix = 0, rank = KSEL_, ceq = 0;
    int pdone = -1;
    for(int p=3; p>=0; p--){
        __syncthreads();
        hist[t] = 0;
        __syncthreads();
        unsigned shift = p*8;
        if(p==3){
            #pragma unroll
            for(int j=0;j<4;j++){
                unsigned bin = key[j]>>24;
                unsigned peers = __match_any_sync(0xffffffffu, bin);
                if(lane == __ffs(peers)-1) atomicAdd(&hist[bin], (unsigned)__popc(peers));
            }
            if(act1){
                #pragma unroll
                for(int j=4;j<8;j++){
                    unsigned bin = key[j]>>24;
                    unsigned peers = __match_any_sync(0xffffffffu, bin);
                    if(lane == __ffs(peers)-1) atomicAdd(&hist[bin], (unsigned)__popc(peers));
                }
            }
        } else {
            unsigned pm = 0xFFFFFFFFu << (shift+8);
            #pragma unroll
            for(int j=0;j<4;j++){
                unsigned k = key[j];
                bool act = ((k & pm) == prefix);
                unsigned amask = __ballot_sync(0xffffffffu, act);
                if(act){
                    unsigned bin = (k>>shift)&255u;
                    unsigned peers = __match_any_sync(amask, bin);
                    if(lane == __ffs(peers)-1) atomicAdd(&hist[bin], (unsigned)__popc(peers));
                }
            }
            if(act1){
                #pragma unroll
                for(int j=4;j<8;j++){
                    unsigned k = key[j];
                    bool act = ((k & pm) == prefix);
                    unsigned amask = __ballot_sync(0xffffffffu, act);
                    if(act){
                        unsigned bin = (k>>shift)&255u;
                        unsigned peers = __match_any_sync(amask, bin);
                        if(lane == __ffs(peers)-1) atomicAdd(&hist[bin], (unsigned)__popc(peers));
                    }
                }
            }
        }
        __syncthreads();
        unsigned h = hist[t], v = h;
        #pragma unroll
        for(int o=1;o<32;o<<=1){
            unsigned nv = __shfl_up_sync(0xffffffffu, v, o);
            if(lane >= o) v += nv;
        }
        if(lane==31) wsum[w] = v;
        __syncthreads();
        unsigned wp = 0;
        #pragma unroll
        for(int i=0;i<8;i++) if(i<w) wp += wsum[i];
        unsigned incl = v + wp, excl = incl - h;
        if(incl >= rank && excl < rank){ sel[0]=(unsigned)t; sel[1]=excl; sel[2]=h; }
        __syncthreads();
        prefix |= sel[0] << shift;
        rank   -= sel[1];
        ceq     = sel[2];
        if(ceq == 1 && p > 0){ pdone = p; break; }
    }
    unsigned KT;
    if(pdone > 0){
        unsigned pm2 = 0xFFFFFFFFu << (pdone*8);
        #pragma unroll
        for(int j=0;j<4;j++) if((key[j] & pm2) == prefix) skt = key[j];
        if(act1){
            #pragma unroll
            for(int j=4;j<8;j++) if((key[j] & pm2) == prefix) skt = key[j];
        }
        __syncthreads();
        KT = skt; rank = 1; ceq = 1;
    } else {
        KT = prefix;
    }
    unsigned rzero = rank;

    float z0=0.f, z1=0.f, z2=0.f;
    #pragma unroll
    for(int c=0;c<2;c++){
        if(c==1 && !act1) break;
        int base = (c==0) ? i0 : i1;
        int jb = c*4;
        #pragma unroll
        for(int j=0;j<4;j++){
            int i = base + j;
            unsigned k = key[jb+j];
            if(k < KT) val[jb+j] = 0.f;
            else if(k == KT){
                if(rzero >= ceq) val[jb+j] = 0.f;
                else{
                    unsigned r = 0;
                    for(int jj=0;jj<i;jj++) if(tokey(grow[jj]) == KT) r++;
                    if(r < rzero) val[jb+j] = 0.f;
                }
            }
        }
        const float4* wg = (const float4*)(w_gate + (size_t)base*3);
        float4 f0 = wg[0], f1 = wg[1], f2 = wg[2];
        z0 += val[jb+0]*f0.x + val[jb+1]*f0.w + val[jb+2]*f1.z + val[jb+3]*f2.y;
        z1 += val[jb+0]*f0.y + val[jb+1]*f1.x + val[jb+2]*f1.w + val[jb+3]*f2.z;
        z2 += val[jb+0]*f0.z + val[jb+1]*f1.y + val[jb+2]*f2.x + val[jb+3]*f2.w;
    }
    blk_sum3(z0, z1, z2, rs);
    z0 = rs[0]; z1 = rs[1]; z2 = rs[2];

    if(t==0){
        float mx = fmaxf(z0, fmaxf(z1, z2));
        float e0 = expf(z0-mx), e1 = expf(z1-mx), e2 = expf(z2-mx);
        float s = e0+e1+e2;
        float p[3] = { e0/s, e1/s, e2/s };
        atomicAdd(g_ent, p[0]*logf(p[0]+1e-10f) + p[1]*logf(p[1]+1e-10f) + p[2]*logf(p[2]+1e-10f));
        int o0=0, o1=1, o2=2;
        if(p[o1] > p[o0]){ int tt=o0; o0=o1; o1=tt; }
        if(p[o2] > p[o1]){ int tt=o1; o1=o2; o2=tt; }
        if(p[o1] > p[o0]){ int tt=o0; o0=o1; o1=tt; }
        float sp0=p[o0], sp1=p[o1], sp2=p[o2];
        bool m0f = sp0 > 0.5f, m1f = (sp0+sp1) > 0.5f, m2f = (sp0+sp1+sp2) > 0.5f;
        int j0 = m0f ? 0 : (m1f ? 1 : 2);
        bool k0 = (!m0f) || (j0==0);
        bool k1 = (!m1f) || (j0==1);
        bool k2 = (!m2f) || (j0==2);
        sgv[o0] = k0 ? 1.f : 0.f;
        sgv[o1] = k1 ? 1.f : 0.f;
        sgv[o2] = k2 ? 1.f : 0.f;
        if(k0) atomicAdd(&g_spz[l*3+0], sp0);
        if(k1) atomicAdd(&g_spz[l*3+1], sp1);
        if(k2) atomicAdd(&g_spz[l*3+2], sp2);
    }
    __syncthreads();

    float c0 = sgv[2], c1 = sgv[0]-sgv[2], c2 = sgv[1]-sgv[2];
    const float* mkS = masks + ((size_t)l*3 + 0)*L_;
    const float* mkT = masks + ((size_t)l*3 + 1)*L_;
    float ssum = 0.f;
    #pragma unroll
    for(int c=0;c<2;c++){
        if(c==1 && !act1) break;
        int base = (c==0) ? i0 : i1;
        int jb = c*4;
        float4 S = *(const float4*)(mkS + base);
        float4 T = *(const float4*)(mkT + base);
        float fs[4] = {S.x,S.y,S.z,S.w};
        float ft[4] = {T.x,T.y,T.z,T.w};
        #pragma unroll
        for(int j=0;j<4;j++){
            int i = base + j;
            float fm = c0 + c1*fs[j] + c2*ft[j];
            if(i == l) fm = 1.f;
            float e = __expf(val[jb+j] * fm);
            val[jb+j] = e;
            ssum += e;
        }
    }
    ssum = blk_sum(ssum, rs);
    float inv = 1.f / ssum;
    {
        __nv_bfloat162 p01 = __floats2bfloat162_rn(val[0]*inv, val[1]*inv);
        __nv_bfloat162 p23 = __floats2bfloat162_rn(val[2]*inv, val[3]*inv);
        uint2 o0 = make_uint2(*reinterpret_cast<unsigned*>(&p01),
                              *reinterpret_cast<unsigned*>(&p23));
        *(uint2*)(hrow + i0) = o0;
        if(act1){
            __nv_bfloat162 p45 = __floats2bfloat162_rn(val[4]*inv, val[5]*inv);
            __nv_bfloat162 p67 = __floats2bfloat162_rn(val[6]*inv, val[7]*inv);
            uint2 o1 = make_uint2(*reinterpret_cast<unsigned*>(&p45),
                                  *reinterpret_cast<unsigned*>(&p67));
            *(uint2*)(hrow + i1) = o1;
        }
    }
}

__global__ void res_ln2_kernel(const float* __restrict__ x, const float* __restrict__ g,
                               const float* __restrict__ bta){
    __shared__ float s[32];
    int row = blockIdx.x;
    int t = threadIdx.x;
    const float* xr = x + (size_t)row*D_;
    float a0 = xr[t], a1 = xr[t+256];
    #pragma unroll
    for(int sp=0; sp<4; sp++){
        a0 += g_gout[sp][(size_t)row*D_ + t];
        a1 += g_gout[sp][(size_t)row*D_ + t + 256];
    }
    float mean = blk_sum(a0+a1, s) * (1.f/D_);
    float d0 = a0-mean, d1 = a1-mean;
    float var = blk_sum(d0*d0 + d1*d1, s) * (1.f/D_);
    float inv = rsqrtf(var + 1e-5f);
    float* x1r = g_x1 + (size_t)row*D_;
    __nv_bfloat16* xn2r = g_xn2h + (size_t)row*D_;
    x1r[t]      = a0;
    x1r[t+256]  = a1;
    xn2r[t]     = __float2bfloat16(d0*inv*g[t]     + bta[t]);
    xn2r[t+256] = __float2bfloat16(d1*inv*g[t+256] + bta[t+256]);
}

__global__ void loss_kernel(const float* __restrict__ spz, const float* __restrict__ ent,
                            float* __restrict__ out){
    __shared__ float rs[32];
    float s = 0.f, sq = 0.f;
    for(int i=threadIdx.x; i<L_*3; i+=256){
        float v = spz[i];
        s += v; sq += v*v;
    }
    s  = blk_sum(s, rs);
    sq = blk_sum(sq, rs);
    if(threadIdx.x == 0){
        const float n = (float)(L_*3);
        float mean = s / n;
        float var = (sq - n*mean*mean) / (n - 1.f);
        float loss_imp = var / (mean*mean + 1e-10f);
        float loss_dyn = -ent[0] / 48.f;
        out[0] = loss_imp + 0.1f*loss_dyn;
    }
}

// ---------------- launch ----------------
extern "C" void kernel_launch(void* const* d_in, const int* in_sizes, int n_in,
                              void* d_out, int out_size){
    const float* x      = (const float*)d_in[0];
    const float* masks  = (const float*)d_in[1];
    const float* ln1_g  = (const float*)d_in[2];
    const float* ln1_b  = (const float*)d_in[3];
    const float* w_p1   = (const float*)d_in[4];
    const float* b_p1   = (const float*)d_in[5];
    const float* w_p2   = (const float*)d_in[6];
    const float* b_p2   = (const float*)d_in[7];
    const float* w_gate = (const float*)d_in[8];
    const float* w_gcn  = (const float*)d_in[9];
    const float* b_gcn  = (const float*)d_in[10];
    const float* ln2_g  = (const float*)d_in[11];
    const float* ln2_b  = (const float*)d_in[12];
    const float* w_f1   = (const float*)d_in[13];
    const float* b_f1   = (const float*)d_in[14];
    const float* w_f2   = (const float*)d_in[15];
    const float* b_f2   = (const float*)d_in[16];
    float* out = (float*)d_out;

    void *p_q, *p_k, *p_adj, *p_xnh, *p_xp, *p_x1, *p_xn2h, *p_ffhh, *p_w1t, *p_w2t, *p_wgt, *p_spz, *p_ent;
    cudaGetSymbolAddress(&p_q,    g_q);
    cudaGetSymbolAddress(&p_k,    g_k);
    cudaGetSymbolAddress(&p_adj,  g_adj);
    cudaGetSymbolAddress(&p_xnh,  g_xnh);
    cudaGetSymbolAddress(&p_xp,   g_xp);
    cudaGetSymbolAddress(&p_x1,   g_x1);
    cudaGetSymbolAddress(&p_xn2h, g_xn2h);
    cudaGetSymbolAddress(&p_ffhh, g_ffhh);
    cudaGetSymbolAddress(&p_w1t,  g_w1t);
    cudaGetSymbolAddress(&p_w2t,  g_w2t);
    cudaGetSymbolAddress(&p_wgt,  g_wgt);
    cudaGetSymbolAddress(&p_spz,  g_spz);
    cudaGetSymbolAddress(&p_ent,  g_ent);

    cudaFuncSetAttribute(mma_gemm<128,64,1,1,0,0,1>, cudaFuncAttributeMaxDynamicSharedMemorySize, gemm_smem<128,64,1>());
    cudaFuncSetAttribute(gconv_kernel,               cudaFuncAttributeMaxDynamicSharedMemorySize, GCONV_SMEM);
    cudaFuncSetAttribute(hgemm<128,1,0,1,1>,         cudaFuncAttributeMaxDynamicSharedMemorySize, hgemm_smem<128>());
    cudaFuncSetAttribute(hgemm<64,0,1,1,0>,          cudaFuncAttributeMaxDynamicSharedMemorySize, hgemm_smem<64>());
    cudaFuncSetAttribute(hgemm<64,0,0,1,0>,          cudaFuncAttributeMaxDynamicSharedMemorySize, hgemm_smem<64>());

    // weight transpose+convert to bf16
    tcvt_kernel<<<dim3(DFF_/32, D_/32), 256>>>(w_f1, (__nv_bfloat16*)p_w1t, D_, DFF_);
    tcvt_kernel<<<dim3(D_/32, DFF_/32), 256>>>(w_f2, (__nv_bfloat16*)p_w2t, DFF_, D_);
    tcvt_kernel<<<dim3(D_/32, D_/32), 256>>>(w_gcn, (__nv_bfloat16*)p_wgt, D_, D_);

    // fused LN1 + q/k + stat zeroing (xn out bf16)
    ln1qk_kernel<<<BL_, 512>>>(x, ln1_g, ln1_b, w_p1, b_p1, w_p2, b_p2);

    // xp = xn @ w_gcn + b_gcn: bf16 m16n8k16, out fp32
    hgemm<64,0,0,1,0><<<dim3(D_/64, BL_/64), 256, hgemm_smem<64>()>>>(
        (const __nv_bfloat16*)p_xnh, (const __nv_bfloat16*)p_wgt, b_gcn, nullptr,
        (float*)p_xp, 512, 512, 512, D_);

    // adj = gelu(Q K^T) per bh: M=N=1408, K=64, tf32 tile 128x64
    mma_gemm<128,64,1,1,0,0,1><<<dim3(22,11,16), 256, gemm_smem<128,64,1>()>>>(
        (const float*)p_q, (const float*)p_k, nullptr, nullptr, (float*)p_adj,
        64, 64, 64, L_,
        1, (size_t)L_*64, (size_t)L_*64, 0, (size_t)L_*(size_t)L_, 0, 0);

    topk_gate_fin_kernel<<<BH_*L_, 256>>>(w_gate, masks);

    // gconv: bf16 adj @ fp32 xp, split-K=4
    gconv_kernel<<<dim3(4,11,16), 256, GCONV_SMEM>>>();

    res_ln2_kernel<<<BL_, 256>>>(x, ln2_g, ln2_b);

    // ffh = gelu(xn2 @ w_f1 + b_f1): bf16, out bf16
    hgemm<128,1,0,1,1><<<dim3(DFF_/64, BL_/128), 256, hgemm_smem<128>()>>>(
        (const __nv_bfloat16*)p_xn2h, (const __nv_bfloat16*)p_w1t, b_f1, nullptr,
        p_ffhh, 512, 512, 512, DFF_);

    // out = ffh @ w_f2 + b_f2 + x1: bf16, out fp32
    hgemm<64,0,1,1,0><<<dim3(D_/64, BL_/64), 256, hgemm_smem<64>()>>>(
        (const __nv_bfloat16*)p_ffhh, (const __nv_bfloat16*)p_w2t, b_f2, (const float*)p_x1,
        out, DFF_, DFF_, DFF_, D_);

    if(out_size >= BL_*D_ + 1){
        loss_kernel<<<1, 256>>>((const float*)p_spz, (const float*)p_ent, out + BL_*D_);
    }
}

// round 15
// speedup vs baseline: 1.1031x; 1.1031x over previous
#include <cuda_runtime.h>
#include <cuda_bf16.h>
#include <math.h>

#define B_   2
#define L_   1408
#define D_   512
#define H_   8
#define BH_  16
#define DFF_ 2048
#define BL_  (B_*L_)
#define KSEL_ 704

// ---------------- scratch ----------------
__device__ __nv_bfloat16 g_xnh[BL_*D_];               // LN1 output, bf16 (feeds xp only)
__device__ float g_q[BH_*L_*64];
__device__ float g_k[BH_*L_*64];
__device__ float g_adj[(size_t)BH_*L_*L_];
__device__ __nv_bfloat16 g_adjh[(size_t)BH_*L_*L_];   // softmaxed adj, bf16
__device__ float g_xp[BL_*D_];
__device__ float g_gout[4][BL_*D_];                   // split-K partials
__device__ float g_x1[BL_*D_];
__device__ __nv_bfloat16 g_xn2h[BL_*D_];              // LN2 output, bf16
__device__ __nv_bfloat16 g_ffhh[(size_t)BL_*DFF_];    // gelu(ffn1), bf16
__device__ __nv_bfloat16 g_w1t[DFF_*D_];              // w_f1^T bf16
__device__ __nv_bfloat16 g_w2t[D_*DFF_];              // w_f2^T bf16
__device__ __nv_bfloat16 g_wgt[D_*D_];                // w_gcn^T bf16
__device__ float g_spz[L_*3];
__device__ float g_ent[1];

// ---------------- helpers ----------------
__device__ __forceinline__ float blk_sum(float v, float* s){
    int lane = threadIdx.x & 31, w = threadIdx.x >> 5;
    #pragma unroll
    for(int o=16;o;o>>=1) v += __shfl_down_sync(0xffffffffu, v, o);
    if(lane==0) s[w]=v;
    __syncthreads();
    int nw = blockDim.x >> 5;
    v = (threadIdx.x < nw) ? s[threadIdx.x] : 0.f;
    if(w==0){
        #pragma unroll
        for(int o=16;o;o>>=1) v += __shfl_down_sync(0xffffffffu, v, o);
        if(lane==0) s[0]=v;
    }
    __syncthreads();
    float r = s[0];
    __syncthreads();
    return r;
}

__device__ __forceinline__ void blk_sum3(float z0, float z1, float z2, float* r3){
    int lane = threadIdx.x & 31, w = threadIdx.x >> 5;
    #pragma unroll
    for(int o=16;o;o>>=1){
        z0 += __shfl_down_sync(0xffffffffu, z0, o);
        z1 += __shfl_down_sync(0xffffffffu, z1, o);
        z2 += __shfl_down_sync(0xffffffffu, z2, o);
    }
    if(lane==0){ r3[3+w]=z0; r3[11+w]=z1; r3[19+w]=z2; }
    __syncthreads();
    if(threadIdx.x==0){
        float a=0,b=0,c=0;
        #pragma unroll
        for(int i=0;i<8;i++){ a+=r3[3+i]; b+=r3[11+i]; c+=r3[19+i]; }
        r3[0]=a; r3[1]=b; r3[2]=c;
    }
    __syncthreads();
}

__device__ __forceinline__ float geluf(float x){
    return 0.5f * x * (1.0f + erff(x * 0.7071067811865475f));
}

__device__ __forceinline__ unsigned tokey(float f){
    unsigned u = __float_as_uint(f);
    return (u & 0x80000000u) ? ~u : (u | 0x80000000u);
}

__device__ __forceinline__ void cpa16(void* s, const void* g){
    unsigned sa = (unsigned)__cvta_generic_to_shared(s);
    asm volatile("cp.async.cg.shared.global [%0], [%1], 16;" :: "r"(sa), "l"(g));
}
__device__ __forceinline__ void cp_commit(){ asm volatile("cp.async.commit_group;"); }
__device__ __forceinline__ void cp_wait0(){ asm volatile("cp.async.wait_group 0;"); }

__device__ __forceinline__ void mma_tf32(float c[4], unsigned a0, unsigned a1, unsigned a2, unsigned a3,
                                         unsigned b0, unsigned b1){
    asm volatile("mma.sync.aligned.m16n8k8.row.col.f32.tf32.tf32.f32 "
        "{%0,%1,%2,%3}, {%4,%5,%6,%7}, {%8,%9}, {%0,%1,%2,%3};"
        : "+f"(c[0]), "+f"(c[1]), "+f"(c[2]), "+f"(c[3])
        : "r"(a0), "r"(a1), "r"(a2), "r"(a3), "r"(b0), "r"(b1));
}

__device__ __forceinline__ void mma_bf16(float c[4], unsigned a0, unsigned a1, unsigned a2, unsigned a3,
                                         unsigned b0, unsigned b1){
    asm volatile("mma.sync.aligned.m16n8k16.row.col.f32.bf16.bf16.f32 "
        "{%0,%1,%2,%3}, {%4,%5,%6,%7}, {%8,%9}, {%0,%1,%2,%3};"
        : "+f"(c[0]), "+f"(c[1]), "+f"(c[2]), "+f"(c[3])
        : "r"(a0), "r"(a1), "r"(a2), "r"(a3), "r"(b0), "r"(b1));
}

// ---------------- tf32 GEMM (adj only) ----------------
template<int BM, int BN, int BLAYOUT, int ACT, int RES, int BIAS, int SPLITK>
__global__ void __launch_bounds__(256)
mma_gemm(const float* __restrict__ A, const float* __restrict__ Bsrc,
         const float* __restrict__ bias, const float* __restrict__ res,
         float* __restrict__ C,
         int K, int lda, int ldb, int ldc,
         int zdiv, size_t aB, size_t bOut, size_t bIn,
         size_t cOut, size_t cIn, size_t cSplit)
{
    constexpr int WROWS = BM/32;
    constexpr int WCOLS = 8/WROWS;
    constexpr int NW    = BN/WCOLS;
    constexpr int NFRAG = NW/8;
    constexpr int ASZ = BM*36;
    constexpr int BSZ = (BLAYOUT==1) ? BN*36 : 32*(BN+4);
    constexpr int BNQ = BN/4;
    extern __shared__ float smem[];
    float* As = smem;
    float* Bs = smem + 2*ASZ;

    int z = blockIdx.z;
    const float* Ap = A + (size_t)z*aB;
    const float* Bp = Bsrc + (size_t)(z/zdiv)*bOut + (size_t)(z%zdiv)*bIn;
    const float* resp = RES ? (res + (size_t)(z/zdiv)*cOut + (size_t)(z%zdiv)*cIn) : nullptr;
    float* Cp = C + (size_t)(z/zdiv)*cOut + (size_t)(z%zdiv)*cIn;

    int n0, kBase = 0;
    if(SPLITK > 1){ n0 = 0; kBase = blockIdx.x * K; Cp += (size_t)blockIdx.x * cSplit; }
    else n0 = blockIdx.x*BN;
    int m0 = blockIdx.y*BM;
    int t = threadIdx.x, warp = t>>5, lane = t&31;
    int g = lane>>2, tg = lane&3;
    int wm = (warp/WCOLS)*32, wn = (warp%WCOLS)*NW;

    float acc[2][NFRAG][4] = {};

    auto load_tiles = [&](int buf, int k0){
        float* Ad = As + buf*ASZ;
        float* Bd = Bs + buf*BSZ;
        #pragma unroll
        for(int j=0; j<BM/32; j++){
            int i = t + j*256;
            int m = i>>3, k4 = (i&7)<<2;
            cpa16(&Ad[m*36+k4], Ap + (size_t)(m0+m)*lda + k0 + k4);
        }
        if(BLAYOUT==1){
            #pragma unroll
            for(int j=0; j<BN/32; j++){
                int i = t + j*256;
                int n = i>>3, k4 = (i&7)<<2;
                cpa16(&Bd[n*36+k4], Bp + (size_t)(n0+n)*ldb + k0 + k4);
            }
        } else {
            #pragma unroll
            for(int j=0; j<BN/32; j++){
                int i = t + j*256;
                int k = i/BNQ, n4 = (i%BNQ)*4;
                cpa16(&Bd[k*(BN+4)+n4], Bp + (size_t)(k0+k)*ldb + n0 + n4);
            }
        }
        cp_commit();
    };

    int nIter = K/32;
    load_tiles(0, kBase);
    for(int it=0; it<nIter; it++){
        cp_wait0();
        __syncthreads();
        if(it+1 < nIter) load_tiles((it+1)&1, kBase + (it+1)*32);
        int buf = it&1;
        const float* Ab = As + buf*ASZ;
        const float* Bb = Bs + buf*BSZ;
        #pragma unroll
        for(int ks=0; ks<32; ks+=8){
            unsigned a[2][4];
            #pragma unroll
            for(int mi=0; mi<2; mi++){
                int r0 = wm + mi*16 + g;
                a[mi][0] = __float_as_uint(Ab[r0*36     + ks+tg]);
                a[mi][1] = __float_as_uint(Ab[(r0+8)*36 + ks+tg]);
                a[mi][2] = __float_as_uint(Ab[r0*36     + ks+tg+4]);
                a[mi][3] = __float_as_uint(Ab[(r0+8)*36 + ks+tg+4]);
            }
            #pragma unroll
            for(int nj=0; nj<NFRAG; nj++){
                int n = wn + nj*8 + g;
                unsigned b0, b1;
                if(BLAYOUT==1){ b0 = __float_as_uint(Bb[n*36 + ks+tg]);
                                b1 = __float_as_uint(Bb[n*36 + ks+tg+4]); }
                else          { b0 = __float_as_uint(Bb[(ks+tg)*(BN+4) + n]);
                                b1 = __float_as_uint(Bb[(ks+tg+4)*(BN+4) + n]); }
                #pragma unroll
                for(int mi=0; mi<2; mi++)
                    mma_tf32(acc[mi][nj], a[mi][0],a[mi][1],a[mi][2],a[mi][3], b0,b1);
            }
        }
        __syncthreads();
    }

    #pragma unroll
    for(int mi=0; mi<2; mi++){
        #pragma unroll
        for(int nj=0; nj<NFRAG; nj++){
            int col = n0 + wn + nj*8 + tg*2;
            #pragma unroll
            for(int half=0; half<2; half++){
                int m = m0 + wm + mi*16 + g + half*8;
                float v0 = acc[mi][nj][half*2+0];
                float v1 = acc[mi][nj][half*2+1];
                if(BIAS){ v0 += bias[col]; v1 += bias[col+1]; }
                if(ACT){ v0 = geluf(v0); v1 = geluf(v1); }
                if(RES){
                    v0 += resp[(size_t)m*ldc + col];
                    v1 += resp[(size_t)m*ldc + col+1];
                }
                *(float2*)(Cp + (size_t)m*ldc + col) = make_float2(v0, v1);
            }
        }
    }
}

template<int BM, int BN, int BLAYOUT>
constexpr int gemm_smem(){
    return (2*BM*36 + 2*((BLAYOUT==1) ? BN*36 : 32*(BN+4))) * 4;
}

// ---------------- bf16 m16n8k16 GEMM. A [m][k] bf16, Bn [n][k] bf16, BN=64, BK=64 ----------------
template<int BM, int ACT, int RES, int BIAS, int OUTBF>
__global__ void __launch_bounds__(256)
hgemm(const __nv_bfloat16* __restrict__ A, const __nv_bfloat16* __restrict__ Bn,
      const float* __restrict__ bias, const float* __restrict__ res,
      void* __restrict__ Cv, int K, int lda, int ldb, int ldc)
{
    constexpr int WROWS = BM/32;
    constexpr int WCOLS = 8/WROWS;
    constexpr int NW    = 64/WCOLS;
    constexpr int NFRAG = NW/8;
    constexpr int ASZ = BM*72;
    constexpr int BSZ = 64*72;
    extern __shared__ __nv_bfloat16 hsm[];
    __nv_bfloat16* As = hsm;
    __nv_bfloat16* Bs = hsm + 2*ASZ;

    int n0 = blockIdx.x*64, m0 = blockIdx.y*BM;
    int t = threadIdx.x, warp = t>>5, lane = t&31;
    int g = lane>>2, tg = lane&3;
    int wm = (warp/WCOLS)*32, wn = (warp%WCOLS)*NW;
    float acc[2][NFRAG][4] = {};

    auto load_tiles = [&](int buf, int k0){
        __nv_bfloat16* Ad = As + buf*ASZ;
        __nv_bfloat16* Bd = Bs + buf*BSZ;
        #pragma unroll
        for(int j=0; j<BM/32; j++){
            int i = t + j*256;
            int m = i>>3, kc = (i&7)*8;
            cpa16(&Ad[m*72+kc], A + (size_t)(m0+m)*lda + k0 + kc);
        }
        #pragma unroll
        for(int j=0; j<2; j++){
            int i = t + j*256;
            int n = i>>3, kc = (i&7)*8;
            cpa16(&Bd[n*72+kc], Bn + (size_t)(n0+n)*ldb + k0 + kc);
        }
        cp_commit();
    };

    int nIter = K/64;
    load_tiles(0, 0);
    for(int it=0; it<nIter; it++){
        cp_wait0();
        __syncthreads();
        if(it+1 < nIter) load_tiles((it+1)&1, (it+1)*64);
        int buf = it&1;
        const __nv_bfloat16* Ab = As + buf*ASZ;
        const __nv_bfloat16* Bb = Bs + buf*BSZ;
        #pragma unroll
        for(int ks=0; ks<64; ks+=16){
            unsigned a[2][4];
            #pragma unroll
            for(int mi=0; mi<2; mi++){
                int r0 = wm + mi*16 + g;
                a[mi][0] = *(const unsigned*)(Ab + r0*72     + ks + 2*tg);
                a[mi][1] = *(const unsigned*)(Ab + (r0+8)*72 + ks + 2*tg);
                a[mi][2] = *(const unsigned*)(Ab + r0*72     + ks + 2*tg + 8);
                a[mi][3] = *(const unsigned*)(Ab + (r0+8)*72 + ks + 2*tg + 8);
            }
            #pragma unroll
            for(int nj=0; nj<NFRAG; nj++){
                int n = wn + nj*8 + g;
                unsigned b0 = *(const unsigned*)(Bb + n*72 + ks + 2*tg);
                unsigned b1 = *(const unsigned*)(Bb + n*72 + ks + 2*tg + 8);
                #pragma unroll
                for(int mi=0; mi<2; mi++)
                    mma_bf16(acc[mi][nj], a[mi][0],a[mi][1],a[mi][2],a[mi][3], b0,b1);
            }
        }
        __syncthreads();
    }

    #pragma unroll
    for(int mi=0; mi<2; mi++){
        #pragma unroll
        for(int nj=0; nj<NFRAG; nj++){
            int col = n0 + wn + nj*8 + tg*2;
            #pragma unroll
            for(int half=0; half<2; half++){
                int m = m0 + wm + mi*16 + g + half*8;
                float v0 = acc[mi][nj][half*2+0];
                float v1 = acc[mi][nj][half*2+1];
                if(BIAS){ v0 += bias[col]; v1 += bias[col+1]; }
                if(ACT){ v0 = geluf(v0); v1 = geluf(v1); }
                if(RES){
                    v0 += res[(size_t)m*ldc + col];
                    v1 += res[(size_t)m*ldc + col+1];
                }
                if(OUTBF){
                    __nv_bfloat162 pv = __floats2bfloat162_rn(v0, v1);
                    *(__nv_bfloat162*)((__nv_bfloat16*)Cv + (size_t)m*ldc + col) = pv;
                } else {
                    *(float2*)((float*)Cv + (size_t)m*ldc + col) = make_float2(v0, v1);
                }
            }
        }
    }
}

template<int BM>
constexpr int hgemm_smem(){ return (2*BM*72 + 2*64*72) * 2; }

// ---------------- transpose + fp32->bf16 convert ----------------
__global__ void tcvt_kernel(const float* __restrict__ src, __nv_bfloat16* __restrict__ dst,
                            int R, int C){
    __shared__ float tile[32][33];
    int t = threadIdx.x;
    int tc = t & 31, tr = t >> 5;
    int rb = blockIdx.y*32, cb = blockIdx.x*32;
    #pragma unroll
    for(int j=0;j<4;j++){
        int rl = tr + j*8;
        tile[rl][tc] = src[(size_t)(rb+rl)*C + cb + tc];
    }
    __syncthreads();
    #pragma unroll
    for(int j=0;j<4;j++){
        int cl = tr + j*8;
        dst[(size_t)(cb+cl)*R + rb + tc] = __float2bfloat16(tile[tc][cl]);
    }
}

// ---------------- gconv: A = bf16 adj, B = fp32 xp, tf32 MMA, split-K=4 ----------------
__global__ void __launch_bounds__(256)
gconv_kernel(){
    constexpr int ASZ = 128*36;
    constexpr int BSZ = 32*68;
    extern __shared__ float smem[];
    float* As = smem;
    float* Bs = smem + 2*ASZ;

    int bh = blockIdx.z, b = bh >> 3, h = bh & 7;
    int m0 = blockIdx.y*128;
    int kBase = blockIdx.x*352;
    const __nv_bfloat16* Ap = g_adjh + ((size_t)bh*L_ + m0)*L_;
    const float* Bp = g_xp + (size_t)b*L_*D_ + h*64;
    float* Cp = g_gout[blockIdx.x] + ((size_t)b*L_ + m0)*D_ + h*64;

    int t = threadIdx.x, warp = t>>5, lane = t&31;
    int g = lane>>2, tg = lane&3;
    int wm = (warp>>1)*32, wn = (warp&1)*32;
    float acc[2][4][4] = {};

    int am = t>>1, ak = (t&1)*16;
    uint4 areg0, areg1;
    auto ldgA = [&](int k0){
        const __nv_bfloat16* p = Ap + (size_t)am*L_ + k0 + ak;
        areg0 = *(const uint4*)(p);
        areg1 = *(const uint4*)(p+8);
    };
    auto stsA = [&](int buf){
        float* Ad = As + buf*ASZ + am*36 + ak;
        unsigned u[8] = {areg0.x,areg0.y,areg0.z,areg0.w, areg1.x,areg1.y,areg1.z,areg1.w};
        float f[16];
        #pragma unroll
        for(int q=0;q<8;q++){
            __nv_bfloat162 hv = *reinterpret_cast<__nv_bfloat162*>(&u[q]);
            float2 fv = __bfloat1622float2(hv);
            f[q*2]=fv.x; f[q*2+1]=fv.y;
        }
        #pragma unroll
        for(int q=0;q<4;q++)
            *(float4*)(Ad + q*4) = make_float4(f[q*4],f[q*4+1],f[q*4+2],f[q*4+3]);
    };
    auto ldB = [&](int buf, int k0){
        float* Bd = Bs + buf*BSZ;
        #pragma unroll
        for(int j=0;j<2;j++){
            int i = t + j*256;
            int k = i>>4, n4 = (i&15)<<2;
            cpa16(&Bd[k*68+n4], Bp + (size_t)(k0+k)*D_ + n4);
        }
        cp_commit();
    };

    ldgA(kBase);
    ldB(0, kBase);
    for(int it=0; it<11; it++){
        stsA(it&1);
        cp_wait0();
        __syncthreads();
        if(it+1 < 11){ ldgA(kBase + (it+1)*32); ldB((it+1)&1, kBase + (it+1)*32); }
        int buf = it&1;
        const float* Ab = As + buf*ASZ;
        const float* Bb = Bs + buf*BSZ;
        #pragma unroll
        for(int ks=0; ks<32; ks+=8){
            unsigned a[2][4];
            #pragma unroll
            for(int mi=0; mi<2; mi++){
                int r0 = wm + mi*16 + g;
                a[mi][0] = __float_as_uint(Ab[r0*36     + ks+tg]);
                a[mi][1] = __float_as_uint(Ab[(r0+8)*36 + ks+tg]);
                a[mi][2] = __float_as_uint(Ab[r0*36     + ks+tg+4]);
                a[mi][3] = __float_as_uint(Ab[(r0+8)*36 + ks+tg+4]);
            }
            #pragma unroll
            for(int nj=0; nj<4; nj++){
                int n = wn + nj*8 + g;
                unsigned b0 = __float_as_uint(Bb[(ks+tg)*68 + n]);
                unsigned b1 = __float_as_uint(Bb[(ks+tg+4)*68 + n]);
                #pragma unroll
                for(int mi=0; mi<2; mi++)
                    mma_tf32(acc[mi][nj], a[mi][0],a[mi][1],a[mi][2],a[mi][3], b0,b1);
            }
        }
        __syncthreads();
    }

    #pragma unroll
    for(int mi=0; mi<2; mi++){
        #pragma unroll
        for(int nj=0; nj<4; nj++){
            int col = wn + nj*8 + tg*2;
            #pragma unroll
            for(int half=0; half<2; half++){
                int m = wm + mi*16 + g + half*8;
                *(float2*)(Cp + (size_t)m*D_ + col) =
                    make_float2(acc[mi][nj][half*2+0], acc[mi][nj][half*2+1]);
            }
        }
    }
}
constexpr int GCONV_SMEM = (2*128*36 + 2*32*68) * 4;

// ---------------- fused LN1 + q/k projection + stat zeroing (xn out bf16) ----------------
__global__ void ln1qk_kernel(const float* __restrict__ x, const float* __restrict__ g,
                             const float* __restrict__ bta,
                             const float* __restrict__ w1, const float* __restrict__ b1,
                             const float* __restrict__ w2, const float* __restrict__ b2){
    __shared__ float xr[512];
    __shared__ float W1[4096];
    __shared__ float W2[4096];
    __shared__ float s[32];
    int row = blockIdx.x;
    int t = threadIdx.x;                 // 512
    float v = x[(size_t)row*D_ + t];
    for(int i=t;i<4096;i+=512){ W1[i]=w1[i]; W2[i]=w2[i]; }
    float mean = blk_sum(v, s) * (1.f/D_);
    float d = v - mean;
    float var = blk_sum(d*d, s) * (1.f/D_);
    float inv = rsqrtf(var + 1e-5f);
    float xnv = d*inv*g[t] + bta[t];
    xr[t] = xnv;
    g_xnh[(size_t)row*D_ + t] = __float2bfloat16(xnv);
    __syncthreads();
    int h = t >> 6, j = t & 63;
    const float* xv = xr + h*64;
    float a1 = b1[j], a2 = b2[j];
    #pragma unroll
    for(int d2=0; d2<64; d2++){
        float vv = xv[d2];
        a1 += vv * W1[d2*64+j];
        a2 += vv * W2[d2*64+j];
    }
    int b = row / L_, l = row % L_;
    size_t o = (((size_t)b*H_ + h)*L_ + l)*64 + j;
    g_q[o] = a1; g_k[o] = a2;
    if(row == 0){
        for(int i=t;i<L_*3;i+=512) g_spz[i] = 0.f;
        if(t == 0) g_ent[0] = 0.f;
    }
}

// fused: top-k sparsify + MoE gating + loss stats + mask mix + row softmax (bf16 out)
// register-resident; plain per-thread histogram atomics (R13 winner).
__global__ void __launch_bounds__(256)
topk_gate_fin_kernel(const float* __restrict__ w_gate,
                     const float* __restrict__ masks){
    __shared__ unsigned hist[256];
    __shared__ unsigned wsum[8];
    __shared__ float rs[32];
    __shared__ unsigned sel[3];
    __shared__ unsigned skt;
    __shared__ float sgv[3];
    int row = blockIdx.x;         // bh*L + l
    int l = row % L_;
    int t = threadIdx.x;          // 256
    int lane = t & 31, w = t >> 5;
    float* grow = g_adj + (size_t)row*L_;
    __nv_bfloat16* hrow = g_adjh + (size_t)row*L_;
    bool act1 = (t < 96);
    int i0 = 4*t, i1 = 1024 + 4*t;

    float val[8];
    unsigned key[8];
    {
        float4 v0 = *(const float4*)(grow + i0);
        val[0]=v0.x; val[1]=v0.y; val[2]=v0.z; val[3]=v0.w;
        if(act1){
            float4 v1 = *(const float4*)(grow + i1);
            val[4]=v1.x; val[5]=v1.y; val[6]=v1.z; val[7]=v1.w;
        } else { val[4]=val[5]=val[6]=val[7]=0.f; }
        #pragma unroll
        for(int j=0;j<8;j++) key[j] = tokey(val[j]);
    }

    unsigned prefix = 0, rank = KSEL_, ceq = 0;
    int pdone = -1;
    for(int p=3; p>=0; p--){
        __syncthreads();
        hist[t] = 0;
        __syncthreads();
        unsigned shift = p*8;
        if(p==3){
            #pragma unroll
            for(int j=0;j<4;j++) atomicAdd(&hist[key[j]>>24], 1u);
            if(act1){
                #pragma unroll
                for(int j=4;j<8;j++) atomicAdd(&hist[key[j]>>24], 1u);
            }
        } else {
            unsigned pm = 0xFFFFFFFFu << (shift+8);
            #pragma unroll
            for(int j=0;j<4;j++){
                unsigned k = key[j];
                if((k & pm) == prefix) atomicAdd(&hist[(k>>shift)&255u], 1u);
            }
            if(act1){
                #pragma unroll
                for(int j=4;j<8;j++){
                    unsigned k = key[j];
                    if((k & pm) == prefix) atomicAdd(&hist[(k>>shift)&255u], 1u);
                }
            }
        }
        __syncthreads();
        unsigned h = hist[t], v = h;
        #pragma unroll
        for(int o=1;o<32;o<<=1){
            unsigned nv = __shfl_up_sync(0xffffffffu, v, o);
            if(lane >= o) v += nv;
        }
        if(lane==31) wsum[w] = v;
        __syncthreads();
        unsigned wp = 0;
        #pragma unroll
        for(int i=0;i<8;i++) if(i<w) wp += wsum[i];
        unsigned incl = v + wp, excl = incl - h;
        if(incl >= rank && excl < rank){ sel[0]=(unsigned)t; sel[1]=excl; sel[2]=h; }
        __syncthreads();
        prefix |= sel[0] << shift;
        rank   -= sel[1];
        ceq     = sel[2];
        if(ceq == 1 && p > 0){ pdone = p; break; }
    }
    unsigned KT;
    if(pdone > 0){
        unsigned pm2 = 0xFFFFFFFFu << (pdone*8);
        #pragma unroll
        for(int j=0;j<4;j++) if((key[j] & pm2) == prefix) skt = key[j];
        if(act1){
            #pragma unroll
            for(int j=4;j<8;j++) if((key[j] & pm2) == prefix) skt = key[j];
        }
        __syncthreads();
        KT = skt; rank = 1; ceq = 1;
    } else {
        KT = prefix;
    }
    unsigned rzero = rank;

    float z0=0.f, z1=0.f, z2=0.f;
    #pragma unroll
    for(int c=0;c<2;c++){
        if(c==1 && !act1) break;
        int base = (c==0) ? i0 : i1;
        int jb = c*4;
        #pragma unroll
        for(int j=0;j<4;j++){
            int i = base + j;
            unsigned k = key[jb+j];
            if(k < KT) val[jb+j] = 0.f;
            else if(k == KT){
                if(rzero >= ceq) val[jb+j] = 0.f;
                else{
                    unsigned r = 0;
                    for(int jj=0;jj<i;jj++) if(tokey(grow[jj]) == KT) r++;
                    if(r < rzero) val[jb+j] = 0.f;
                }
            }
        }
        const float4* wg = (const float4*)(w_gate + (size_t)base*3);
        float4 f0 = wg[0], f1 = wg[1], f2 = wg[2];
        z0 += val[jb+0]*f0.x + val[jb+1]*f0.w + val[jb+2]*f1.z + val[jb+3]*f2.y;
        z1 += val[jb+0]*f0.y + val[jb+1]*f1.x + val[jb+2]*f1.w + val[jb+3]*f2.z;
        z2 += val[jb+0]*f0.z + val[jb+1]*f1.y + val[jb+2]*f2.x + val[jb+3]*f2.w;
    }
    blk_sum3(z0, z1, z2, rs);
    z0 = rs[0]; z1 = rs[1]; z2 = rs[2];

    if(t==0){
        float mx = fmaxf(z0, fmaxf(z1, z2));
        float e0 = expf(z0-mx), e1 = expf(z1-mx), e2 = expf(z2-mx);
        float s = e0+e1+e2;
        float p[3] = { e0/s, e1/s, e2/s };
        atomicAdd(g_ent, p[0]*logf(p[0]+1e-10f) + p[1]*logf(p[1]+1e-10f) + p[2]*logf(p[2]+1e-10f));
        int o0=0, o1=1, o2=2;
        if(p[o1] > p[o0]){ int tt=o0; o0=o1; o1=tt; }
        if(p[o2] > p[o1]){ int tt=o1; o1=o2; o2=tt; }
        if(p[o1] > p[o0]){ int tt=o0; o0=o1; o1=tt; }
        float sp0=p[o0], sp1=p[o1], sp2=p[o2];
        bool m0f = sp0 > 0.5f, m1f = (sp0+sp1) > 0.5f, m2f = (sp0+sp1+sp2) > 0.5f;
        int j0 = m0f ? 0 : (m1f ? 1 : 2);
        bool k0 = (!m0f) || (j0==0);
        bool k1 = (!m1f) || (j0==1);
        bool k2 = (!m2f) || (j0==2);
        sgv[o0] = k0 ? 1.f : 0.f;
        sgv[o1] = k1 ? 1.f : 0.f;
        sgv[o2] = k2 ? 1.f : 0.f;
        if(k0) atomicAdd(&g_spz[l*3+0], sp0);
        if(k1) atomicAdd(&g_spz[l*3+1], sp1);
        if(k2) atomicAdd(&g_spz[l*3+2], sp2);
    }
    __syncthreads();

    float c0 = sgv[2], c1 = sgv[0]-sgv[2], c2 = sgv[1]-sgv[2];
    const float* mkS = masks + ((size_t)l*3 + 0)*L_;
    const float* mkT = masks + ((size_t)l*3 + 1)*L_;
    float ssum = 0.f;
    #pragma unroll
    for(int c=0;c<2;c++){
        if(c==1 && !act1) break;
        int base = (c==0) ? i0 : i1;
        int jb = c*4;
        float4 S = *(const float4*)(mkS + base);
        float4 T = *(const float4*)(mkT + base);
        float fs[4] = {S.x,S.y,S.z,S.w};
        float ft[4] = {T.x,T.y,T.z,T.w};
        #pragma unroll
        for(int j=0;j<4;j++){
            int i = base + j;
            float fm = c0 + c1*fs[j] + c2*ft[j];
            if(i == l) fm = 1.f;
            float e = __expf(val[jb+j] * fm);
            val[jb+j] = e;
            ssum += e;
        }
    }
    ssum = blk_sum(ssum, rs);
    float inv = 1.f / ssum;
    {
        __nv_bfloat162 p01 = __floats2bfloat162_rn(val[0]*inv, val[1]*inv);
        __nv_bfloat162 p23 = __floats2bfloat162_rn(val[2]*inv, val[3]*inv);
        uint2 o0 = make_uint2(*reinterpret_cast<unsigned*>(&p01),
                              *reinterpret_cast<unsigned*>(&p23));
        *(uint2*)(hrow + i0) = o0;
        if(act1){
            __nv_bfloat162 p45 = __floats2bfloat162_rn(val[4]*inv, val[5]*inv);
            __nv_bfloat162 p67 = __floats2bfloat162_rn(val[6]*inv, val[7]*inv);
            uint2 o1 = make_uint2(*reinterpret_cast<unsigned*>(&p45),
                                  *reinterpret_cast<unsigned*>(&p67));
            *(uint2*)(hrow + i1) = o1;
        }
    }
}

__global__ void res_ln2_kernel(const float* __restrict__ x, const float* __restrict__ g,
                               const float* __restrict__ bta){
    __shared__ float s[32];
    int row = blockIdx.x;
    int t = threadIdx.x;
    const float* xr = x + (size_t)row*D_;
    float a0 = xr[t], a1 = xr[t+256];
    #pragma unroll
    for(int sp=0; sp<4; sp++){
        a0 += g_gout[sp][(size_t)row*D_ + t];
        a1 += g_gout[sp][(size_t)row*D_ + t + 256];
    }
    float mean = blk_sum(a0+a1, s) * (1.f/D_);
    float d0 = a0-mean, d1 = a1-mean;
    float var = blk_sum(d0*d0 + d1*d1, s) * (1.f/D_);
    float inv = rsqrtf(var + 1e-5f);
    float* x1r = g_x1 + (size_t)row*D_;
    __nv_bfloat16* xn2r = g_xn2h + (size_t)row*D_;
    x1r[t]      = a0;
    x1r[t+256]  = a1;
    xn2r[t]     = __float2bfloat16(d0*inv*g[t]     + bta[t]);
    xn2r[t+256] = __float2bfloat16(d1*inv*g[t+256] + bta[t+256]);
}

__global__ void loss_kernel(const float* __restrict__ spz, const float* __restrict__ ent,
                            float* __restrict__ out){
    __shared__ float rs[32];
    float s = 0.f, sq = 0.f;
    for(int i=threadIdx.x; i<L_*3; i+=256){
        float v = spz[i];
        s += v; sq += v*v;
    }
    s  = blk_sum(s, rs);
    sq = blk_sum(sq, rs);
    if(threadIdx.x == 0){
        const float n = (float)(L_*3);
        float mean = s / n;
        float var = (sq - n*mean*mean) / (n - 1.f);
        float loss_imp = var / (mean*mean + 1e-10f);
        float loss_dyn = -ent[0] / 48.f;
        out[0] = loss_imp + 0.1f*loss_dyn;
    }
}

// ---------------- launch ----------------
extern "C" void kernel_launch(void* const* d_in, const int* in_sizes, int n_in,
                              void* d_out, int out_size){
    const float* x      = (const float*)d_in[0];
    const float* masks  = (const float*)d_in[1];
    const float* ln1_g  = (const float*)d_in[2];
    const float* ln1_b  = (const float*)d_in[3];
    const float* w_p1   = (const float*)d_in[4];
    const float* b_p1   = (const float*)d_in[5];
    const float* w_p2   = (const float*)d_in[6];
    const float* b_p2   = (const float*)d_in[7];
    const float* w_gate = (const float*)d_in[8];
    const float* w_gcn  = (const float*)d_in[9];
    const float* b_gcn  = (const float*)d_in[10];
    const float* ln2_g  = (const float*)d_in[11];
    const float* ln2_b  = (const float*)d_in[12];
    const float* w_f1   = (const float*)d_in[13];
    const float* b_f1   = (const float*)d_in[14];
    const float* w_f2   = (const float*)d_in[15];
    const float* b_f2   = (const float*)d_in[16];
    float* out = (float*)d_out;

    void *p_q, *p_k, *p_adj, *p_xnh, *p_xp, *p_x1, *p_xn2h, *p_ffhh, *p_w1t, *p_w2t, *p_wgt, *p_spz, *p_ent;
    cudaGetSymbolAddress(&p_q,    g_q);
    cudaGetSymbolAddress(&p_k,    g_k);
    cudaGetSymbolAddress(&p_adj,  g_adj);
    cudaGetSymbolAddress(&p_xnh,  g_xnh);
    cudaGetSymbolAddress(&p_xp,   g_xp);
    cudaGetSymbolAddress(&p_x1,   g_x1);
    cudaGetSymbolAddress(&p_xn2h, g_xn2h);
    cudaGetSymbolAddress(&p_ffhh, g_ffhh);
    cudaGetSymbolAddress(&p_w1t,  g_w1t);
    cudaGetSymbolAddress(&p_w2t,  g_w2t);
    cudaGetSymbolAddress(&p_wgt,  g_wgt);
    cudaGetSymbolAddress(&p_spz,  g_spz);
    cudaGetSymbolAddress(&p_ent,  g_ent);

    cudaFuncSetAttribute(mma_gemm<128,64,1,1,0,0,1>, cudaFuncAttributeMaxDynamicSharedMemorySize, gemm_smem<128,64,1>());
    cudaFuncSetAttribute(gconv_kernel,               cudaFuncAttributeMaxDynamicSharedMemorySize, GCONV_SMEM);
    cudaFuncSetAttribute(hgemm<128,1,0,1,1>,         cudaFuncAttributeMaxDynamicSharedMemorySize, hgemm_smem<128>());
    cudaFuncSetAttribute(hgemm<64,0,1,1,0>,          cudaFuncAttributeMaxDynamicSharedMemorySize, hgemm_smem<64>());
    cudaFuncSetAttribute(hgemm<64,0,0,1,0>,          cudaFuncAttributeMaxDynamicSharedMemorySize, hgemm_smem<64>());

    // weight transpose+convert to bf16
    tcvt_kernel<<<dim3(DFF_/32, D_/32), 256>>>(w_f1, (__nv_bfloat16*)p_w1t, D_, DFF_);
    tcvt_kernel<<<dim3(D_/32, DFF_/32), 256>>>(w_f2, (__nv_bfloat16*)p_w2t, DFF_, D_);
    tcvt_kernel<<<dim3(D_/32, D_/32), 256>>>(w_gcn, (__nv_bfloat16*)p_wgt, D_, D_);

    // fused LN1 + q/k + stat zeroing (xn out bf16)
    ln1qk_kernel<<<BL_, 512>>>(x, ln1_g, ln1_b, w_p1, b_p1, w_p2, b_p2);

    // xp = xn @ w_gcn + b_gcn: bf16 m16n8k16, out fp32
    hgemm<64,0,0,1,0><<<dim3(D_/64, BL_/64), 256, hgemm_smem<64>()>>>(
        (const __nv_bfloat16*)p_xnh, (const __nv_bfloat16*)p_wgt, b_gcn, nullptr,
        (float*)p_xp, 512, 512, 512, D_);

    // adj = gelu(Q K^T) per bh: M=N=1408, K=64, tf32 tile 128x64
    mma_gemm<128,64,1,1,0,0,1><<<dim3(22,11,16), 256, gemm_smem<128,64,1>()>>>(
        (const float*)p_q, (const float*)p_k, nullptr, nullptr, (float*)p_adj,
        64, 64, 64, L_,
        1, (size_t)L_*64, (size_t)L_*64, 0, (size_t)L_*(size_t)L_, 0, 0);

    topk_gate_fin_kernel<<<BH_*L_, 256>>>(w_gate, masks);

    // gconv: bf16 adj @ fp32 xp, split-K=4
    gconv_kernel<<<dim3(4,11,16), 256, GCONV_SMEM>>>();

    res_ln2_kernel<<<BL_, 256>>>(x, ln2_g, ln2_b);

    // ffh = gelu(xn2 @ w_f1 + b_f1): bf16, out bf16
    hgemm<128,1,0,1,1><<<dim3(DFF_/64, BL_/128), 256, hgemm_smem<128>()>>>(
        (const __nv_bfloat16*)p_xn2h, (const __nv_bfloat16*)p_w1t, b_f1, nullptr,
        p_ffhh, 512, 512, 512, DFF_);

    // out = ffh @ w_f2 + b_f2 + x1: bf16, out fp32
    hgemm<64,0,1,1,0><<<dim3(D_/64, BL_/64), 256, hgemm_smem<64>()>>>(
        (const __nv_bfloat16*)p_ffhh, (const __nv_bfloat16*)p_w2t, b_f2, (const float*)p_x1,
        out, DFF_, DFF_, DFF_, D_);

    if(out_size >= BL_*D_ + 1){
        loss_kernel<<<1, 256>>>((const float*)p_spz, (const float*)p_ent, out + BL_*D_);
    }
}